// round 16
// baseline (speedup 1.0000x reference)
#include <cuda_runtime.h>
#include <cuda_fp16.h>
#include <cstdint>
#include <cstddef>

// Problem constants
#define BATCH   512
#define NATOMS  32
#define DIM     512
#define NROWS   (BATCH * NATOMS)     // 16384
#define LHID    6
#define LOUT    6

// ---------------------------------------------------------------------------
// Scratch (static device globals; allocation-free per harness rules)
// ---------------------------------------------------------------------------
__device__ __align__(16) __half g_Vh [(size_t)NROWS * DIM];        // act split ping
__device__ __align__(16) __half g_Vl [(size_t)NROWS * DIM];
__device__ __align__(16) __half g_Uh [(size_t)NROWS * DIM];        // act split pong
__device__ __align__(16) __half g_Ul [(size_t)NROWS * DIM];
__device__ float  g_rn [(size_t)LHID * NROWS];                     // per-layer row sumsq
__device__ __align__(16) __half g_Wth[(size_t)LHID * DIM * DIM];   // feature W hi
__device__ __align__(16) __half g_Wtl[(size_t)LHID * DIM * DIM];   // feature W lo
__device__ __align__(16) __half g_Woth[(size_t)LOUT * DIM * DIM];  // MLP W hi
__device__ __align__(16) __half g_Wotl[(size_t)LOUT * DIM * DIM];  // MLP W lo
__device__ __align__(16) __half g_Mh0[(size_t)BATCH * DIM];        // mol split ping
__device__ __align__(16) __half g_Ml0[(size_t)BATCH * DIM];
__device__ __align__(16) __half g_Mh1[(size_t)BATCH * DIM];        // mol split pong
__device__ __align__(16) __half g_Ml1[(size_t)BATCH * DIM];
__device__ float  g_molf[(size_t)BATCH * DIM];                     // fp32 MLP out

// ---------------------------------------------------------------------------
// PTX helpers
// ---------------------------------------------------------------------------
__device__ __forceinline__ uint32_t smem_to_u32(const void* p) {
    uint32_t a;
    asm("{ .reg .u64 t; cvta.to.shared.u64 t, %1; cvt.u32.u64 %0, t; }" : "=r"(a) : "l"(p));
    return a;
}
#define CP_ASYNC16(dst, src) \
    asm volatile("cp.async.cg.shared.global [%0], [%1], 16;" :: "r"(dst), "l"(src))
#define CP_COMMIT() asm volatile("cp.async.commit_group;" ::: "memory")
#define CP_WAIT0()  asm volatile("cp.async.wait_group 0;" ::: "memory")
#define LDSM4(R0, R1, R2, R3, addr) \
    asm volatile("ldmatrix.sync.aligned.m8n8.x4.shared.b16 {%0,%1,%2,%3}, [%4];" \
        : "=r"(R0), "=r"(R1), "=r"(R2), "=r"(R3) : "r"(addr))

__device__ __forceinline__ void mma16816(float* d, const uint32_t* a, const uint32_t* b) {
    asm volatile(
        "mma.sync.aligned.m16n8k16.row.col.f32.f16.f16.f32 "
        "{%0,%1,%2,%3}, {%4,%5,%6,%7}, {%8,%9}, {%0,%1,%2,%3};"
        : "+f"(d[0]), "+f"(d[1]), "+f"(d[2]), "+f"(d[3])
        : "r"(a[0]), "r"(a[1]), "r"(a[2]), "r"(a[3]), "r"(b[0]), "r"(b[1]));
}
__device__ __forceinline__ void mma16816_f16(uint32_t* d, const uint32_t* a, const uint32_t* b) {
    asm volatile(
        "mma.sync.aligned.m16n8k16.row.col.f16.f16.f16.f16 "
        "{%0,%1}, {%2,%3,%4,%5}, {%6,%7}, {%0,%1};"
        : "+r"(d[0]), "+r"(d[1])
        : "r"(a[0]), "r"(a[1]), "r"(a[2]), "r"(a[3]), "r"(b[0]), "r"(b[1]));
}

__device__ __forceinline__ void split_store(__half* dh, __half* dl, int off,
                                            float x0, float x1, float x2, float x3) {
    __half h0 = __float2half_rn(x0), h1 = __float2half_rn(x1);
    __half h2 = __float2half_rn(x2), h3 = __float2half_rn(x3);
    *(__half2*)(dh + off)     = __halves2half2(h0, h1);
    *(__half2*)(dh + off + 2) = __halves2half2(h2, h3);
    *(__half2*)(dl + off)     = __halves2half2(__float2half_rn(x0 - __half2float(h0)),
                                               __float2half_rn(x1 - __half2float(h1)));
    *(__half2*)(dl + off + 2) = __halves2half2(__float2half_rn(x2 - __half2float(h2)),
                                               __float2half_rn(x3 - __half2float(h3)));
}

// ---------------------------------------------------------------------------
// 0a) Zero the per-layer row-norm accumulators (required every graph replay)
// ---------------------------------------------------------------------------
__global__ void zero_rn_kernel() {
    g_rn[(size_t)blockIdx.x * 256 + threadIdx.x] = 0.0f;
}

// ---------------------------------------------------------------------------
// 0b) Weight transpose + fp16 hi/lo split: dst[l][n][k] = split(src[l][k][n])
// ---------------------------------------------------------------------------
__global__ void transpose_split_w(const float* __restrict__ W,
                                  __half* __restrict__ dh,
                                  __half* __restrict__ dl) {
    __shared__ float t[32][33];
    const int l  = blockIdx.z;
    const int k0 = blockIdx.y * 32, n0 = blockIdx.x * 32;
    const int tx = threadIdx.x, ty = threadIdx.y;     // 32 x 8
    const float* src = W + (size_t)l * DIM * DIM;
#pragma unroll
    for (int i = 0; i < 4; i++)
        t[ty + i * 8][tx] = src[(size_t)(k0 + ty + i * 8) * DIM + n0 + tx];
    __syncthreads();
#pragma unroll
    for (int i = 0; i < 4; i++) {
        float v = t[tx][ty + i * 8];
        size_t dst = (size_t)l * DIM * DIM + (size_t)(n0 + ty + i * 8) * DIM + k0 + tx;
        __half hi = __float2half_rn(v);
        dh[dst] = hi;
        dl[dst] = __float2half_rn(v - __half2float(hi));
    }
}

// ---------------------------------------------------------------------------
// 1) Gather + split: Vh/Vl[row,:] = split(embed[fp[row],:])
// ---------------------------------------------------------------------------
__global__ void gather_embed(const int* __restrict__ fp,
                             const float* __restrict__ embed) {
    int row = blockIdx.x;
    int f = fp[row];
    float4 v = ((const float4*)(embed + (size_t)f * DIM))[threadIdx.x];
    split_store(g_Vh + (size_t)row * DIM, g_Vl + (size_t)row * DIM,
                threadIdx.x * 4, v.x, v.y, v.z, v.w);
}

// ---------------------------------------------------------------------------
// 2) fused GEMM + message passing + deferred normalization:
//    h  = relu((A@W) * invnorm_in + bf)      (input norm applied in epilogue)
//    H2 = h + A_blockdiag @ h -> fp16 split out + row sumsq accumulated
//    CTA tile 64x128 (2 molecules x 128 cols), 8 warps of 32x32, KC=64.
// ---------------------------------------------------------------------------
#define KC2     64
#define NCH     (DIM / KC2)
#define A_OPB   (64  * KC2 * 2)
#define B_OPB   (128 * KC2 * 2)
#define STAGEB  (2 * A_OPB + 2 * B_OPB)
#define HG_SMEM (2 * STAGEB)
#define HG_THREADS 256

__device__ __forceinline__ void hg_issue(
    int c, int m0, int n0, uint32_t smem_u32, int tid,
    const __half* __restrict__ Ah, const __half* __restrict__ Al,
    const __half* __restrict__ Bh, const __half* __restrict__ Bl) {
    const int k0 = c * KC2;
    const uint32_t sbase = smem_u32 + (c & 1) * STAGEB;
#pragma unroll
    for (int i = 0; i < 2; i++) {
        int idx = tid + i * HG_THREADS;
        int r = idx >> 3, ch = idx & 7;
        uint32_t doff = (uint32_t)(r * 128 + ((ch ^ (r & 7)) * 16));
        size_t go = (size_t)(m0 + r) * DIM + k0 + ch * 8;
        CP_ASYNC16(sbase + 0 * A_OPB + doff, Ah + go);
        CP_ASYNC16(sbase + 1 * A_OPB + doff, Al + go);
    }
#pragma unroll
    for (int i = 0; i < 4; i++) {
        int idx = tid + i * HG_THREADS;
        int r = idx >> 3, ch = idx & 7;
        uint32_t doff = (uint32_t)(r * 128 + ((ch ^ (r & 7)) * 16));
        size_t go = (size_t)(n0 + r) * DIM + k0 + ch * 8;
        CP_ASYNC16(sbase + 2 * A_OPB + 0 * B_OPB + doff, Bh + go);
        CP_ASYNC16(sbase + 2 * A_OPB + 1 * B_OPB + doff, Bl + go);
    }
}

__global__ void __launch_bounds__(HG_THREADS, 2)
hgemm_fused(const __half* __restrict__ Ah, const __half* __restrict__ Al,
            const __half* __restrict__ Bh, const __half* __restrict__ Bl,
            const float* __restrict__ bias, const float* __restrict__ adj,
            const float* __restrict__ rn_in,   // nullptr for layer 0
            float* __restrict__ rn_out,
            __half* __restrict__ Oh, __half* __restrict__ Ol) {
    extern __shared__ __half hsm[];
    const uint32_t smem_u32 = smem_to_u32(hsm);
    const int tid = threadIdx.x;
    const int lane = tid & 31, wid = tid >> 5;
    const int m0 = blockIdx.y * 64, n0 = blockIdx.x * 128;
    const int wm = (wid >> 2) * 32, wn = (wid & 3) * 32;
    const int g = lane >> 2, tg = lane & 3;
    const int lrow = lane & 15, lsel = lane >> 4, lsw = lrow & 7;

    const uint32_t rA0 = (uint32_t)((wm + lrow) * 128);
    const uint32_t rA1 = (uint32_t)((wm + 16 + lrow) * 128);
    const uint32_t rB0 = (uint32_t)((wn + lrow) * 128);
    const uint32_t rB1 = (uint32_t)((wn + 16 + lrow) * 128);

    float acc[2][4][4];
    uint32_t accc[2][4][2];
#pragma unroll
    for (int i = 0; i < 2; i++)
#pragma unroll
        for (int j = 0; j < 4; j++) {
#pragma unroll
            for (int r = 0; r < 4; r++) acc[i][j][r] = 0.0f;
            accc[i][j][0] = 0u; accc[i][j][1] = 0u;
        }

    hg_issue(0, m0, n0, smem_u32, tid, Ah, Al, Bh, Bl);
    CP_COMMIT();

    for (int c = 0; c < NCH; c++) {
        CP_WAIT0();
        __syncthreads();
        if (c + 1 < NCH) {
            hg_issue(c + 1, m0, n0, smem_u32, tid, Ah, Al, Bh, Bl);
            CP_COMMIT();
        }
        const uint32_t sb = smem_u32 + (c & 1) * STAGEB;
        const uint32_t aH = sb, aL = sb + A_OPB;
        const uint32_t bH = sb + 2 * A_OPB, bL = bH + B_OPB;

#pragma unroll
        for (int ks = 0; ks < KC2 / 16; ks++) {
            const uint32_t swz = (uint32_t)((((ks * 2) + lsel) ^ lsw) * 16);
            uint32_t a_hi[2][4], a_lo[2][4], b_hi[2][4], b_lo[2][4];

            LDSM4(a_hi[0][0], a_hi[0][1], a_hi[0][2], a_hi[0][3], aH + rA0 + swz);
            LDSM4(a_hi[1][0], a_hi[1][1], a_hi[1][2], a_hi[1][3], aH + rA1 + swz);
            LDSM4(b_hi[0][0], b_hi[0][1], b_hi[0][2], b_hi[0][3], bH + rB0 + swz);
            LDSM4(b_hi[1][0], b_hi[1][1], b_hi[1][2], b_hi[1][3], bH + rB1 + swz);
#pragma unroll
            for (int mf = 0; mf < 2; mf++)
#pragma unroll
                for (int nf = 0; nf < 4; nf++) {
                    int p = nf >> 1, o = nf & 1;
                    uint32_t bf[2] = { b_hi[p][o], b_hi[p][o + 2] };
                    mma16816(acc[mf][nf], a_hi[mf], bf);
                }
            LDSM4(b_lo[0][0], b_lo[0][1], b_lo[0][2], b_lo[0][3], bL + rB0 + swz);
            LDSM4(b_lo[1][0], b_lo[1][1], b_lo[1][2], b_lo[1][3], bL + rB1 + swz);
#pragma unroll
            for (int mf = 0; mf < 2; mf++)
#pragma unroll
                for (int nf = 0; nf < 4; nf++) {
                    int p = nf >> 1, o = nf & 1;
                    uint32_t bf[2] = { b_lo[p][o], b_lo[p][o + 2] };
                    mma16816_f16(accc[mf][nf], a_hi[mf], bf);
                }
            LDSM4(a_lo[0][0], a_lo[0][1], a_lo[0][2], a_lo[0][3], aL + rA0 + swz);
            LDSM4(a_lo[1][0], a_lo[1][1], a_lo[1][2], a_lo[1][3], aL + rA1 + swz);
#pragma unroll
            for (int mf = 0; mf < 2; mf++)
#pragma unroll
                for (int nf = 0; nf < 4; nf++) {
                    int p = nf >> 1, o = nf & 1;
                    uint32_t bf[2] = { b_hi[p][o], b_hi[p][o + 2] };
                    mma16816_f16(accc[mf][nf], a_lo[mf], bf);
                }
        }
        __syncthreads();
    }

    // ---- Fused epilogue ----
    float* hs      = (float*)hsm;         // [64][130]
    float* adjs    = hs + 64 * 130;       // [2][32][32]
    float* rowpart = adjs + 2048;         // [64] partial sumsq

    // h = relu(acc*invn_in + corr*invn_in + bias)
#pragma unroll
    for (int mf = 0; mf < 2; mf++) {
        int row = wm + mf * 16 + g;
        float inv0 = 1.0f, inv1 = 1.0f;
        if (rn_in) {
            inv0 = 1.0f / fmaxf(sqrtf(rn_in[m0 + row]), 1e-12f);
            inv1 = 1.0f / fmaxf(sqrtf(rn_in[m0 + row + 8]), 1e-12f);
        }
#pragma unroll
        for (int nf = 0; nf < 4; nf++) {
            int col = wn + nf * 8 + tg * 2;
            float b0 = bias[n0 + col], b1 = bias[n0 + col + 1];
            __half2 c01 = *(__half2*)&accc[mf][nf][0];
            __half2 c23 = *(__half2*)&accc[mf][nf][1];
            float2 o0, o1;
            o0.x = fmaxf((acc[mf][nf][0] + __low2float(c01))  * inv0 + b0, 0.0f);
            o0.y = fmaxf((acc[mf][nf][1] + __high2float(c01)) * inv0 + b1, 0.0f);
            o1.x = fmaxf((acc[mf][nf][2] + __low2float(c23))  * inv1 + b0, 0.0f);
            o1.y = fmaxf((acc[mf][nf][3] + __high2float(c23)) * inv1 + b1, 0.0f);
            *(float2*)&hs[row * 130 + col] = o0;
            *(float2*)&hs[(row + 8) * 130 + col] = o1;
        }
    }
    {
        const float* asrc = adj + (size_t)m0 * 32;
#pragma unroll
        for (int i = 0; i < 8; i++)
            adjs[tid + i * 256] = asrc[tid + i * 256];
        if (tid < 64) rowpart[tid] = 0.0f;
    }
    __syncthreads();

    // H2 = h + A.h ; split-store + sumsq accumulation
    {
        const int mol = wid >> 2;
        const int c   = (wid & 3) * 32 + lane;
        float hm[32];
#pragma unroll
        for (int m = 0; m < 32; m++)
            hm[m] = hs[(mol * 32 + m) * 130 + c];
        const float* ar = adjs + mol * 1024;
        const size_t base = (size_t)(m0 + mol * 32) * DIM + n0 + c;
#pragma unroll
        for (int n = 0; n < 32; n++) {
            float s = hm[n];
#pragma unroll
            for (int mq = 0; mq < 8; mq++) {
                float4 a4 = *(const float4*)&ar[n * 32 + mq * 4];
                s = fmaf(a4.x, hm[mq * 4 + 0], s);
                s = fmaf(a4.y, hm[mq * 4 + 1], s);
                s = fmaf(a4.z, hm[mq * 4 + 2], s);
                s = fmaf(a4.w, hm[mq * 4 + 3], s);
            }
            __half hi = __float2half_rn(s);
            Oh[base + (size_t)n * DIM] = hi;
            Ol[base + (size_t)n * DIM] = __float2half_rn(s - __half2float(hi));
            float ssq = s * s;
#pragma unroll
            for (int o = 16; o; o >>= 1) ssq += __shfl_xor_sync(0xFFFFFFFFu, ssq, o);
            if (lane == 0) atomicAdd(&rowpart[mol * 32 + n], ssq);
        }
    }
    __syncthreads();
    if (tid < 64) atomicAdd(&rn_out[m0 + tid], rowpart[tid]);
}

// ---------------------------------------------------------------------------
// 3) final_pool: invn from precomputed sumsq; mol = mean_n(H2[n]*invn[n])
//    -> fp16 split (Mh0, Ml0)
// ---------------------------------------------------------------------------
#define POOL_SMEM ((NATOMS * DIM + NATOMS) * (int)sizeof(float))

__global__ void final_pool_kernel(const __half* __restrict__ Hh,
                                  const __half* __restrict__ Hl,
                                  const float* __restrict__ rn) {
    extern __shared__ float sm[];
    float* h    = sm;                     // [32][512]
    float* invn = sm + NATOMS * DIM;      // [32]
    const int b   = blockIdx.x;
    const int tid = threadIdx.x;          // 256 threads

    {
        const __half2* sh = (const __half2*)(Hh + (size_t)b * NATOMS * DIM);
        const __half2* sl = (const __half2*)(Hl + (size_t)b * NATOMS * DIM);
#pragma unroll
        for (int i = 0; i < (NATOMS * DIM / 2) / 256; i++) {
            int idx = tid + i * 256;
            float2 vh = __half22float2(sh[idx]);
            float2 vl = __half22float2(sl[idx]);
            h[idx * 2 + 0] = vh.x + vl.x;
            h[idx * 2 + 1] = vh.y + vl.y;
        }
        if (tid < NATOMS)
            invn[tid] = 1.0f / fmaxf(sqrtf(rn[(size_t)b * NATOMS + tid]), 1e-12f);
    }
    __syncthreads();

#pragma unroll
    for (int j = 0; j < 2; j++) {
        int dd = tid + j * 256;
        float s = 0.0f;
#pragma unroll
        for (int n = 0; n < NATOMS; n++)
            s = fmaf(h[n * DIM + dd], invn[n], s);
        s *= (1.0f / NATOMS);
        __half hi = __float2half_rn(s);
        g_Mh0[(size_t)b * DIM + dd] = hi;
        g_Ml0[(size_t)b * DIM + dd] = __float2half_rn(s - __half2float(hi));
    }
}

// ---------------------------------------------------------------------------
// 4) MLP tensor GEMM (unchanged from R15): out = relu(M @ Wo + bo)
// ---------------------------------------------------------------------------
#define ML_A_OPB (32 * KC2 * 2)
#define ML_B_OPB (128 * KC2 * 2)
#define ML_STAGEB (2 * ML_A_OPB + 2 * ML_B_OPB)
#define ML_SMEM (2 * ML_STAGEB)

__device__ __forceinline__ void ml_issue(
    int c, int m0, int n0, uint32_t smem_u32, int tid,
    const __half* __restrict__ Ah, const __half* __restrict__ Al,
    const __half* __restrict__ Bh, const __half* __restrict__ Bl) {
    const int k0 = c * KC2;
    const uint32_t sbase = smem_u32 + (c & 1) * ML_STAGEB;
    {
        int idx = tid;
        int r = idx >> 3, ch = idx & 7;
        uint32_t doff = (uint32_t)(r * 128 + ((ch ^ (r & 7)) * 16));
        size_t go = (size_t)(m0 + r) * DIM + k0 + ch * 8;
        CP_ASYNC16(sbase + 0 * ML_A_OPB + doff, Ah + go);
        CP_ASYNC16(sbase + 1 * ML_A_OPB + doff, Al + go);
    }
#pragma unroll
    for (int i = 0; i < 4; i++) {
        int idx = tid + i * 256;
        int r = idx >> 3, ch = idx & 7;
        uint32_t doff = (uint32_t)(r * 128 + ((ch ^ (r & 7)) * 16));
        size_t go = (size_t)(n0 + r) * DIM + k0 + ch * 8;
        CP_ASYNC16(sbase + 2 * ML_A_OPB + 0 * ML_B_OPB + doff, Bh + go);
        CP_ASYNC16(sbase + 2 * ML_A_OPB + 1 * ML_B_OPB + doff, Bl + go);
    }
}

__global__ void __launch_bounds__(256, 2)
mlp_gemm(const __half* __restrict__ Ah, const __half* __restrict__ Al,
         const __half* __restrict__ Bh, const __half* __restrict__ Bl,
         const float* __restrict__ bias,
         __half* __restrict__ Oh, __half* __restrict__ Ol,
         float* __restrict__ Of) {
    extern __shared__ __half hsm[];
    const uint32_t smem_u32 = smem_to_u32(hsm);
    const int tid = threadIdx.x;
    const int lane = tid & 31, wid = tid >> 5;
    const int m0 = blockIdx.y * 32, n0 = blockIdx.x * 128;
    const int wm = (wid >> 2) * 16, wn = (wid & 3) * 32;
    const int g = lane >> 2, tg = lane & 3;
    const int lrow = lane & 15, lsel = lane >> 4, lsw = lrow & 7;

    const uint32_t rA0 = (uint32_t)((wm + lrow) * 128);
    const uint32_t rB0 = (uint32_t)((wn + lrow) * 128);
    const uint32_t rB1 = (uint32_t)((wn + 16 + lrow) * 128);

    float acc[4][4];
    uint32_t accc[4][2];
#pragma unroll
    for (int j = 0; j < 4; j++) {
#pragma unroll
        for (int r = 0; r < 4; r++) acc[j][r] = 0.0f;
        accc[j][0] = 0u; accc[j][1] = 0u;
    }

    ml_issue(0, m0, n0, smem_u32, tid, Ah, Al, Bh, Bl);
    CP_COMMIT();

    for (int c = 0; c < NCH; c++) {
        CP_WAIT0();
        __syncthreads();
        if (c + 1 < NCH) {
            ml_issue(c + 1, m0, n0, smem_u32, tid, Ah, Al, Bh, Bl);
            CP_COMMIT();
        }
        const uint32_t sb = smem_u32 + (c & 1) * ML_STAGEB;
        const uint32_t aH = sb, aL = sb + ML_A_OPB;
        const uint32_t bH = sb + 2 * ML_A_OPB, bL = bH + ML_B_OPB;

#pragma unroll
        for (int ks = 0; ks < KC2 / 16; ks++) {
            const uint32_t swz = (uint32_t)((((ks * 2) + lsel) ^ lsw) * 16);
            uint32_t a_hi[4], a_lo[4], b_hi[2][4], b_lo[2][4];

            LDSM4(a_hi[0], a_hi[1], a_hi[2], a_hi[3], aH + rA0 + swz);
            LDSM4(b_hi[0][0], b_hi[0][1], b_hi[0][2], b_hi[0][3], bH + rB0 + swz);
            LDSM4(b_hi[1][0], b_hi[1][1], b_hi[1][2], b_hi[1][3], bH + rB1 + swz);
#pragma unroll
            for (int nf = 0; nf < 4; nf++) {
                int p = nf >> 1, o = nf & 1;
                uint32_t bf[2] = { b_hi[p][o], b_hi[p][o + 2] };
                mma16816(acc[nf], a_hi, bf);
            }
            LDSM4(b_lo[0][0], b_lo[0][1], b_lo[0][2], b_lo[0][3], bL + rB0 + swz);
            LDSM4(b_lo[1][0], b_lo[1][1], b_lo[1][2], b_lo[1][3], bL + rB1 + swz);
#pragma unroll
            for (int nf = 0; nf < 4; nf++) {
                int p = nf >> 1, o = nf & 1;
                uint32_t bf[2] = { b_lo[p][o], b_lo[p][o + 2] };
                mma16816_f16(accc[nf], a_hi, bf);
            }
            LDSM4(a_lo[0], a_lo[1], a_lo[2], a_lo[3], aL + rA0 + swz);
#pragma unroll
            for (int nf = 0; nf < 4; nf++) {
                int p = nf >> 1, o = nf & 1;
                uint32_t bf[2] = { b_hi[p][o], b_hi[p][o + 2] };
                mma16816_f16(accc[nf], a_lo, bf);
            }
        }
        __syncthreads();
    }

#pragma unroll
    for (int nf = 0; nf < 4; nf++) {
        int col = n0 + wn + nf * 8 + tg * 2;
        float b0 = bias[col], b1 = bias[col + 1];
        __half2 c01 = *(__half2*)&accc[nf][0];
        __half2 c23 = *(__half2*)&accc[nf][1];
        int r0 = m0 + wm + g;
        float v0 = fmaxf(acc[nf][0] + __low2float(c01)  + b0, 0.0f);
        float v1 = fmaxf(acc[nf][1] + __high2float(c01) + b1, 0.0f);
        float v2 = fmaxf(acc[nf][2] + __low2float(c23)  + b0, 0.0f);
        float v3 = fmaxf(acc[nf][3] + __high2float(c23) + b1, 0.0f);
        float2 w0 = {v0, v1}, w1 = {v2, v3};
        *(float2*)(Of + (size_t)r0 * DIM + col) = w0;
        *(float2*)(Of + (size_t)(r0 + 8) * DIM + col) = w1;
        __half h0 = __float2half_rn(v0), h1 = __float2half_rn(v1);
        __half h2 = __float2half_rn(v2), h3 = __float2half_rn(v3);
        *(__half2*)(Oh + (size_t)r0 * DIM + col) = __halves2half2(h0, h1);
        *(__half2*)(Ol + (size_t)r0 * DIM + col) =
            __halves2half2(__float2half_rn(v0 - __half2float(h0)),
                           __float2half_rn(v1 - __half2float(h1)));
        *(__half2*)(Oh + (size_t)(r0 + 8) * DIM + col) = __halves2half2(h2, h3);
        *(__half2*)(Ol + (size_t)(r0 + 8) * DIM + col) =
            __halves2half2(__float2half_rn(v2 - __half2float(h2)),
                           __float2half_rn(v3 - __half2float(h3)));
    }
}

// ---------------------------------------------------------------------------
// 5) Final projection: out[b] = molf[b,:] . Wp + bp
// ---------------------------------------------------------------------------
__global__ void final_kernel(const float* __restrict__ Wp,
                             const float* __restrict__ bp,
                             float* __restrict__ out) {
    int b = blockIdx.x;
    float s = 0.0f;
    for (int d = threadIdx.x; d < DIM; d += 128)
        s = fmaf(g_molf[(size_t)b * DIM + d], Wp[d], s);
    __shared__ float red[4];
#pragma unroll
    for (int o = 16; o; o >>= 1) s += __shfl_down_sync(0xFFFFFFFFu, s, o);
    if ((threadIdx.x & 31) == 0) red[threadIdx.x >> 5] = s;
    __syncthreads();
    if (threadIdx.x == 0)
        out[b] = red[0] + red[1] + red[2] + red[3] + bp[0];
}

// ---------------------------------------------------------------------------
// Launcher
// ---------------------------------------------------------------------------
extern "C" void kernel_launch(void* const* d_in, const int* in_sizes, int n_in,
                              void* d_out, int out_size) {
    const int*   fp    = (const int*)  d_in[0];
    const float* adj   = (const float*)d_in[1];
    const float* embed = (const float*)d_in[2];
    const float* Wf    = (const float*)d_in[3];
    const float* bf    = (const float*)d_in[4];
    const float* Wo    = (const float*)d_in[5];
    const float* bo    = (const float*)d_in[6];
    const float* Wp    = (const float*)d_in[7];
    const float* bp    = (const float*)d_in[8];
    float* out = (float*)d_out;

    float *Rn, *Molf;
    __half *Vh, *Vl, *Uh, *Ul, *Wth, *Wtl, *Woth, *Wotl, *Mh0, *Ml0, *Mh1, *Ml1;
    cudaGetSymbolAddress((void**)&Vh,   g_Vh);
    cudaGetSymbolAddress((void**)&Vl,   g_Vl);
    cudaGetSymbolAddress((void**)&Uh,   g_Uh);
    cudaGetSymbolAddress((void**)&Ul,   g_Ul);
    cudaGetSymbolAddress((void**)&Rn,   g_rn);
    cudaGetSymbolAddress((void**)&Wth,  g_Wth);
    cudaGetSymbolAddress((void**)&Wtl,  g_Wtl);
    cudaGetSymbolAddress((void**)&Woth, g_Woth);
    cudaGetSymbolAddress((void**)&Wotl, g_Wotl);
    cudaGetSymbolAddress((void**)&Mh0,  g_Mh0);
    cudaGetSymbolAddress((void**)&Ml0,  g_Ml0);
    cudaGetSymbolAddress((void**)&Mh1,  g_Mh1);
    cudaGetSymbolAddress((void**)&Ml1,  g_Ml1);
    cudaGetSymbolAddress((void**)&Molf, g_molf);

    cudaFuncSetAttribute(hgemm_fused,
                         cudaFuncAttributeMaxDynamicSharedMemorySize, HG_SMEM);
    cudaFuncSetAttribute(mlp_gemm,
                         cudaFuncAttributeMaxDynamicSharedMemorySize, ML_SMEM);
    cudaFuncSetAttribute(final_pool_kernel,
                         cudaFuncAttributeMaxDynamicSharedMemorySize, POOL_SMEM);

    zero_rn_kernel<<<LHID * NROWS / 256, 256>>>();                          // 0
    transpose_split_w<<<dim3(16, 16, LHID), dim3(32, 8)>>>(Wf, Wth, Wtl);   // 1
    transpose_split_w<<<dim3(16, 16, LOUT), dim3(32, 8)>>>(Wo, Woth, Wotl); // 2
    gather_embed<<<NROWS, 128>>>(fp, embed);                                // 3

    __half *ah = Vh, *al = Vl, *oh = Uh, *ol = Ul;
    for (int l = 0; l < LHID; l++) {
        hgemm_fused<<<dim3(DIM / 128, NROWS / 64), HG_THREADS, HG_SMEM>>>(
            ah, al,
            Wth + (size_t)l * DIM * DIM, Wtl + (size_t)l * DIM * DIM,
            bf + (size_t)l * DIM, adj,
            (l == 0) ? (const float*)nullptr : (Rn + (size_t)(l - 1) * NROWS),
            Rn + (size_t)l * NROWS,
            oh, ol);                                   // launch 4 (l0), 5 (l1) <- ncu idx5
        __half* t;
        t = ah; ah = oh; oh = t;
        t = al; al = ol; ol = t;
    }
    // after 6 swaps, last output pair is (ah, al)
    final_pool_kernel<<<BATCH, 256, POOL_SMEM>>>(ah, al, Rn + (size_t)(LHID - 1) * NROWS);

    __half *sh = Mh0, *sl = Ml0, *dh = Mh1, *dl = Ml1;
    for (int i = 0; i < LOUT; i++) {
        mlp_gemm<<<dim3(DIM / 128, BATCH / 32), 256, ML_SMEM>>>(
            sh, sl,
            Woth + (size_t)i * DIM * DIM, Wotl + (size_t)i * DIM * DIM,
            bo + (size_t)i * DIM, dh, dl, Molf);
        __half* t;
        t = sh; sh = dh; dh = t;
        t = sl; sl = dl; dl = t;
    }

    final_kernel<<<BATCH, 128>>>(Wp, bp, out);
}

// round 17
// speedup vs baseline: 1.1055x; 1.1055x over previous
#include <cuda_runtime.h>
#include <cuda_fp16.h>
#include <cstdint>
#include <cstddef>

// Problem constants
#define BATCH   512
#define NATOMS  32
#define DIM     512
#define NROWS   (BATCH * NATOMS)     // 16384
#define LHID    6
#define LOUT    6

// ---------------------------------------------------------------------------
// Scratch (static device globals; allocation-free per harness rules)
// ---------------------------------------------------------------------------
__device__ float  g_H [(size_t)NROWS * DIM];                       // 32 MB H2 out
__device__ __align__(16) __half g_Vh [(size_t)NROWS * DIM];        // 16 MB act hi
__device__ __align__(16) __half g_Vl [(size_t)NROWS * DIM];        // 16 MB act lo
__device__ __align__(16) __half g_Wth[(size_t)LHID * DIM * DIM];   // feature W hi
__device__ __align__(16) __half g_Wtl[(size_t)LHID * DIM * DIM];   // feature W lo
__device__ __align__(16) __half g_Woth[(size_t)LOUT * DIM * DIM];  // MLP W hi
__device__ __align__(16) __half g_Wotl[(size_t)LOUT * DIM * DIM];  // MLP W lo
__device__ __align__(16) __half g_Mh0[(size_t)BATCH * DIM];        // mol split ping
__device__ __align__(16) __half g_Ml0[(size_t)BATCH * DIM];
__device__ __align__(16) __half g_Mh1[(size_t)BATCH * DIM];        // mol split pong
__device__ __align__(16) __half g_Ml1[(size_t)BATCH * DIM];
__device__ float  g_molf[(size_t)BATCH * DIM];                     // fp32 MLP out

// ---------------------------------------------------------------------------
// PTX helpers
// ---------------------------------------------------------------------------
__device__ __forceinline__ uint32_t smem_to_u32(const void* p) {
    uint32_t a;
    asm("{ .reg .u64 t; cvta.to.shared.u64 t, %1; cvt.u32.u64 %0, t; }" : "=r"(a) : "l"(p));
    return a;
}
#define CP_ASYNC16(dst, src) \
    asm volatile("cp.async.cg.shared.global [%0], [%1], 16;" :: "r"(dst), "l"(src))
#define CP_COMMIT() asm volatile("cp.async.commit_group;" ::: "memory")
#define CP_WAIT0()  asm volatile("cp.async.wait_group 0;" ::: "memory")
#define LDSM4(R0, R1, R2, R3, addr) \
    asm volatile("ldmatrix.sync.aligned.m8n8.x4.shared.b16 {%0,%1,%2,%3}, [%4];" \
        : "=r"(R0), "=r"(R1), "=r"(R2), "=r"(R3) : "r"(addr))

__device__ __forceinline__ void mma16816(float* d, const uint32_t* a, const uint32_t* b) {
    asm volatile(
        "mma.sync.aligned.m16n8k16.row.col.f32.f16.f16.f32 "
        "{%0,%1,%2,%3}, {%4,%5,%6,%7}, {%8,%9}, {%0,%1,%2,%3};"
        : "+f"(d[0]), "+f"(d[1]), "+f"(d[2]), "+f"(d[3])
        : "r"(a[0]), "r"(a[1]), "r"(a[2]), "r"(a[3]), "r"(b[0]), "r"(b[1]));
}
__device__ __forceinline__ void mma16816_f16(uint32_t* d, const uint32_t* a, const uint32_t* b) {
    asm volatile(
        "mma.sync.aligned.m16n8k16.row.col.f16.f16.f16.f16 "
        "{%0,%1}, {%2,%3,%4,%5}, {%6,%7}, {%0,%1};"
        : "+r"(d[0]), "+r"(d[1])
        : "r"(a[0]), "r"(a[1]), "r"(a[2]), "r"(a[3]), "r"(b[0]), "r"(b[1]));
}

__device__ __forceinline__ void split_store(__half* dh, __half* dl, int off,
                                            float x0, float x1, float x2, float x3) {
    __half h0 = __float2half_rn(x0), h1 = __float2half_rn(x1);
    __half h2 = __float2half_rn(x2), h3 = __float2half_rn(x3);
    *(__half2*)(dh + off)     = __halves2half2(h0, h1);
    *(__half2*)(dh + off + 2) = __halves2half2(h2, h3);
    *(__half2*)(dl + off)     = __halves2half2(__float2half_rn(x0 - __half2float(h0)),
                                               __float2half_rn(x1 - __half2float(h1)));
    *(__half2*)(dl + off + 2) = __halves2half2(__float2half_rn(x2 - __half2float(h2)),
                                               __float2half_rn(x3 - __half2float(h3)));
}

// ---------------------------------------------------------------------------
// 0) Weight transpose + fp16 hi/lo split: dst[l][n][k] = split(src[l][k][n])
// ---------------------------------------------------------------------------
__global__ void transpose_split_w(const float* __restrict__ W,
                                  __half* __restrict__ dh,
                                  __half* __restrict__ dl) {
    __shared__ float t[32][33];
    const int l  = blockIdx.z;
    const int k0 = blockIdx.y * 32, n0 = blockIdx.x * 32;
    const int tx = threadIdx.x, ty = threadIdx.y;     // 32 x 8
    const float* src = W + (size_t)l * DIM * DIM;
#pragma unroll
    for (int i = 0; i < 4; i++)
        t[ty + i * 8][tx] = src[(size_t)(k0 + ty + i * 8) * DIM + n0 + tx];
    __syncthreads();
#pragma unroll
    for (int i = 0; i < 4; i++) {
        float v = t[tx][ty + i * 8];
        size_t dst = (size_t)l * DIM * DIM + (size_t)(n0 + ty + i * 8) * DIM + k0 + tx;
        __half hi = __float2half_rn(v);
        dh[dst] = hi;
        dl[dst] = __float2half_rn(v - __half2float(hi));
    }
}

// ---------------------------------------------------------------------------
// 1) Gather + split: Vh/Vl[row,:] = split(embed[fp[row],:])
//    256 threads, 2 rows per block.
// ---------------------------------------------------------------------------
__global__ void gather_embed(const int* __restrict__ fp,
                             const float* __restrict__ embed) {
    int row = blockIdx.x * 2 + (threadIdx.x >> 7);
    int t   = threadIdx.x & 127;
    int f = fp[row];
    float4 v = ((const float4*)(embed + (size_t)f * DIM))[t];
    split_store(g_Vh + (size_t)row * DIM, g_Vl + (size_t)row * DIM,
                t * 4, v.x, v.y, v.z, v.w);
}

// ---------------------------------------------------------------------------
// 2) fused GEMM + message passing:
//    h = relu(V @ Wf + bf); H2 = h + A.h   (CTA 64x128, 8 warps, KC=64)
// ---------------------------------------------------------------------------
#define KC2     64
#define NCH     (DIM / KC2)
#define A_OPB   (64  * KC2 * 2)
#define B_OPB   (128 * KC2 * 2)
#define STAGEB  (2 * A_OPB + 2 * B_OPB)
#define HG_SMEM (2 * STAGEB)
#define HG_THREADS 256

__device__ __forceinline__ void hg_issue(
    int c, int m0, int n0, uint32_t smem_u32, int tid,
    const __half* __restrict__ Ah, const __half* __restrict__ Al,
    const __half* __restrict__ Bh, const __half* __restrict__ Bl) {
    const int k0 = c * KC2;
    const uint32_t sbase = smem_u32 + (c & 1) * STAGEB;
#pragma unroll
    for (int i = 0; i < 2; i++) {
        int idx = tid + i * HG_THREADS;
        int r = idx >> 3, ch = idx & 7;
        uint32_t doff = (uint32_t)(r * 128 + ((ch ^ (r & 7)) * 16));
        size_t go = (size_t)(m0 + r) * DIM + k0 + ch * 8;
        CP_ASYNC16(sbase + 0 * A_OPB + doff, Ah + go);
        CP_ASYNC16(sbase + 1 * A_OPB + doff, Al + go);
    }
#pragma unroll
    for (int i = 0; i < 4; i++) {
        int idx = tid + i * HG_THREADS;
        int r = idx >> 3, ch = idx & 7;
        uint32_t doff = (uint32_t)(r * 128 + ((ch ^ (r & 7)) * 16));
        size_t go = (size_t)(n0 + r) * DIM + k0 + ch * 8;
        CP_ASYNC16(sbase + 2 * A_OPB + 0 * B_OPB + doff, Bh + go);
        CP_ASYNC16(sbase + 2 * A_OPB + 1 * B_OPB + doff, Bl + go);
    }
}

__global__ void __launch_bounds__(HG_THREADS, 2)
hgemm_fused(const __half* __restrict__ Ah, const __half* __restrict__ Al,
            const __half* __restrict__ Bh, const __half* __restrict__ Bl,
            const float* __restrict__ bias, const float* __restrict__ adj,
            float* __restrict__ C) {
    extern __shared__ __half hsm[];
    const uint32_t smem_u32 = smem_to_u32(hsm);
    const int tid = threadIdx.x;
    const int lane = tid & 31, wid = tid >> 5;
    const int m0 = blockIdx.y * 64, n0 = blockIdx.x * 128;
    const int wm = (wid >> 2) * 32, wn = (wid & 3) * 32;
    const int g = lane >> 2, tg = lane & 3;
    const int lrow = lane & 15, lsel = lane >> 4, lsw = lrow & 7;

    const uint32_t rA0 = (uint32_t)((wm + lrow) * 128);
    const uint32_t rA1 = (uint32_t)((wm + 16 + lrow) * 128);
    const uint32_t rB0 = (uint32_t)((wn + lrow) * 128);
    const uint32_t rB1 = (uint32_t)((wn + 16 + lrow) * 128);

    float acc[2][4][4];
    uint32_t accc[2][4][2];
#pragma unroll
    for (int i = 0; i < 2; i++)
#pragma unroll
        for (int j = 0; j < 4; j++) {
#pragma unroll
            for (int r = 0; r < 4; r++) acc[i][j][r] = 0.0f;
            accc[i][j][0] = 0u; accc[i][j][1] = 0u;
        }

    hg_issue(0, m0, n0, smem_u32, tid, Ah, Al, Bh, Bl);
    CP_COMMIT();

    for (int c = 0; c < NCH; c++) {
        CP_WAIT0();
        __syncthreads();
        if (c + 1 < NCH) {
            hg_issue(c + 1, m0, n0, smem_u32, tid, Ah, Al, Bh, Bl);
            CP_COMMIT();
        }
        const uint32_t sb = smem_u32 + (c & 1) * STAGEB;
        const uint32_t aH = sb, aL = sb + A_OPB;
        const uint32_t bH = sb + 2 * A_OPB, bL = bH + B_OPB;

#pragma unroll
        for (int ks = 0; ks < KC2 / 16; ks++) {
            const uint32_t swz = (uint32_t)((((ks * 2) + lsel) ^ lsw) * 16);
            uint32_t a_hi[2][4], a_lo[2][4], b_hi[2][4], b_lo[2][4];

            LDSM4(a_hi[0][0], a_hi[0][1], a_hi[0][2], a_hi[0][3], aH + rA0 + swz);
            LDSM4(a_hi[1][0], a_hi[1][1], a_hi[1][2], a_hi[1][3], aH + rA1 + swz);
            LDSM4(b_hi[0][0], b_hi[0][1], b_hi[0][2], b_hi[0][3], bH + rB0 + swz);
            LDSM4(b_hi[1][0], b_hi[1][1], b_hi[1][2], b_hi[1][3], bH + rB1 + swz);
#pragma unroll
            for (int mf = 0; mf < 2; mf++)
#pragma unroll
                for (int nf = 0; nf < 4; nf++) {
                    int p = nf >> 1, o = nf & 1;
                    uint32_t bf[2] = { b_hi[p][o], b_hi[p][o + 2] };
                    mma16816(acc[mf][nf], a_hi[mf], bf);
                }
            LDSM4(b_lo[0][0], b_lo[0][1], b_lo[0][2], b_lo[0][3], bL + rB0 + swz);
            LDSM4(b_lo[1][0], b_lo[1][1], b_lo[1][2], b_lo[1][3], bL + rB1 + swz);
#pragma unroll
            for (int mf = 0; mf < 2; mf++)
#pragma unroll
                for (int nf = 0; nf < 4; nf++) {
                    int p = nf >> 1, o = nf & 1;
                    uint32_t bf[2] = { b_lo[p][o], b_lo[p][o + 2] };
                    mma16816_f16(accc[mf][nf], a_hi[mf], bf);
                }
            LDSM4(a_lo[0][0], a_lo[0][1], a_lo[0][2], a_lo[0][3], aL + rA0 + swz);
            LDSM4(a_lo[1][0], a_lo[1][1], a_lo[1][2], a_lo[1][3], aL + rA1 + swz);
#pragma unroll
            for (int mf = 0; mf < 2; mf++)
#pragma unroll
                for (int nf = 0; nf < 4; nf++) {
                    int p = nf >> 1, o = nf & 1;
                    uint32_t bf[2] = { b_hi[p][o], b_hi[p][o + 2] };
                    mma16816_f16(accc[mf][nf], a_lo[mf], bf);
                }
        }
        __syncthreads();
    }

    // Fused epilogue: h = relu(acc + corr + bias); H2 = h + A.h
    float* hs   = (float*)hsm;            // [64][130]
    float* adjs = hs + 64 * 130;          // [2][32][32]

#pragma unroll
    for (int mf = 0; mf < 2; mf++) {
        int row = wm + mf * 16 + g;
#pragma unroll
        for (int nf = 0; nf < 4; nf++) {
            int col = wn + nf * 8 + tg * 2;
            float b0 = bias[n0 + col], b1 = bias[n0 + col + 1];
            __half2 c01 = *(__half2*)&accc[mf][nf][0];
            __half2 c23 = *(__half2*)&accc[mf][nf][1];
            float2 o0, o1;
            o0.x = fmaxf(acc[mf][nf][0] + __low2float(c01)  + b0, 0.0f);
            o0.y = fmaxf(acc[mf][nf][1] + __high2float(c01) + b1, 0.0f);
            o1.x = fmaxf(acc[mf][nf][2] + __low2float(c23)  + b0, 0.0f);
            o1.y = fmaxf(acc[mf][nf][3] + __high2float(c23) + b1, 0.0f);
            *(float2*)&hs[row * 130 + col] = o0;
            *(float2*)&hs[(row + 8) * 130 + col] = o1;
        }
    }
    {
        const float* asrc = adj + (size_t)m0 * 32;
#pragma unroll
        for (int i = 0; i < 8; i++)
            adjs[tid + i * 256] = asrc[tid + i * 256];
    }
    __syncthreads();

    {
        const int mol = wid >> 2;
        const int c   = (wid & 3) * 32 + lane;
        float hm[32];
#pragma unroll
        for (int m = 0; m < 32; m++)
            hm[m] = hs[(mol * 32 + m) * 130 + c];
        const float* ar = adjs + mol * 1024;
        float* dst = C + (size_t)(m0 + mol * 32) * DIM + n0 + c;
#pragma unroll
        for (int n = 0; n < 32; n++) {
            float s = hm[n];
#pragma unroll
            for (int mq = 0; mq < 8; mq++) {
                float4 a4 = *(const float4*)&ar[n * 32 + mq * 4];
                s = fmaf(a4.x, hm[mq * 4 + 0], s);
                s = fmaf(a4.y, hm[mq * 4 + 1], s);
                s = fmaf(a4.z, hm[mq * 4 + 2], s);
                s = fmaf(a4.w, hm[mq * 4 + 3], s);
            }
            dst[(size_t)n * DIM] = s;
        }
    }
}

// ---------------------------------------------------------------------------
// 3) norm_split: v = H2/max(||H2||_row, eps) -> Vh, Vl   (warp per row)
// ---------------------------------------------------------------------------
__global__ void norm_split_kernel() {
    const int row  = blockIdx.x * 8 + (threadIdx.x >> 5);
    const int lane = threadIdx.x & 31;
    const float4* src = (const float4*)(g_H + (size_t)row * DIM);
    float4 v[4];
    float ss = 0.0f;
#pragma unroll
    for (int i = 0; i < 4; i++) {
        v[i] = src[lane + i * 32];
        ss = fmaf(v[i].x, v[i].x, ss);
        ss = fmaf(v[i].y, v[i].y, ss);
        ss = fmaf(v[i].z, v[i].z, ss);
        ss = fmaf(v[i].w, v[i].w, ss);
    }
#pragma unroll
    for (int o = 16; o; o >>= 1) ss += __shfl_xor_sync(0xFFFFFFFFu, ss, o);
    const float inv = 1.0f / fmaxf(sqrtf(ss), 1e-12f);
    __half* dh = g_Vh + (size_t)row * DIM;
    __half* dl = g_Vl + (size_t)row * DIM;
#pragma unroll
    for (int i = 0; i < 4; i++)
        split_store(dh, dl, (lane + i * 32) * 4,
                    v[i].x * inv, v[i].y * inv, v[i].z * inv, v[i].w * inv);
}

// ---------------------------------------------------------------------------
// 4) final_pool: mol = mean_n(H2[n]*invn[n]) -> fp16 split (Mh0, Ml0)
// ---------------------------------------------------------------------------
#define POOL_SMEM ((NATOMS * DIM + NATOMS) * (int)sizeof(float))

__global__ void final_pool_kernel() {
    extern __shared__ float sm[];
    float* h    = sm;
    float* invn = sm + NATOMS * DIM;
    const int b   = blockIdx.x;
    const int tid = threadIdx.x;          // 256 threads

    {
        const float4* src = (const float4*)(g_H + (size_t)b * NATOMS * DIM);
        float4* dst = (float4*)h;
#pragma unroll
        for (int i = 0; i < (NATOMS * DIM / 4) / 256; i++)
            dst[tid + i * 256] = src[tid + i * 256];
    }
    __syncthreads();
    {
        const int w = tid >> 5, lane = tid & 31;
        for (int r = w * 4; r < w * 4 + 4; r++) {
            float ss = 0.0f;
#pragma unroll
            for (int i = 0; i < DIM / 32; i++) {
                float x = h[r * DIM + lane + i * 32];
                ss = fmaf(x, x, ss);
            }
#pragma unroll
            for (int o = 16; o; o >>= 1) ss += __shfl_xor_sync(0xFFFFFFFFu, ss, o);
            if (lane == 0) invn[r] = 1.0f / fmaxf(sqrtf(ss), 1e-12f);
        }
    }
    __syncthreads();

#pragma unroll
    for (int j = 0; j < 2; j++) {
        int dd = tid + j * 256;
        float s = 0.0f;
#pragma unroll
        for (int n = 0; n < NATOMS; n++)
            s = fmaf(h[n * DIM + dd], invn[n], s);
        s *= (1.0f / NATOMS);
        __half hi = __float2half_rn(s);
        g_Mh0[(size_t)b * DIM + dd] = hi;
        g_Ml0[(size_t)b * DIM + dd] = __float2half_rn(s - __half2float(hi));
    }
}

// ---------------------------------------------------------------------------
// 5) MLP tensor GEMM: out = relu(M @ Wo + bo), 3-term split.
//    CTA 32x128, 8 warps of 16x32, KC=64. Writes fp16 split + fp32.
// ---------------------------------------------------------------------------
#define ML_A_OPB (32 * KC2 * 2)        // 4096
#define ML_B_OPB (128 * KC2 * 2)       // 16384
#define ML_STAGEB (2 * ML_A_OPB + 2 * ML_B_OPB)   // 40960
#define ML_SMEM (2 * ML_STAGEB)                   // 81920

__device__ __forceinline__ void ml_issue(
    int c, int m0, int n0, uint32_t smem_u32, int tid,
    const __half* __restrict__ Ah, const __half* __restrict__ Al,
    const __half* __restrict__ Bh, const __half* __restrict__ Bl) {
    const int k0 = c * KC2;
    const uint32_t sbase = smem_u32 + (c & 1) * ML_STAGEB;
    {
        int idx = tid;
        int r = idx >> 3, ch = idx & 7;
        uint32_t doff = (uint32_t)(r * 128 + ((ch ^ (r & 7)) * 16));
        size_t go = (size_t)(m0 + r) * DIM + k0 + ch * 8;
        CP_ASYNC16(sbase + 0 * ML_A_OPB + doff, Ah + go);
        CP_ASYNC16(sbase + 1 * ML_A_OPB + doff, Al + go);
    }
#pragma unroll
    for (int i = 0; i < 4; i++) {
        int idx = tid + i * 256;
        int r = idx >> 3, ch = idx & 7;
        uint32_t doff = (uint32_t)(r * 128 + ((ch ^ (r & 7)) * 16));
        size_t go = (size_t)(n0 + r) * DIM + k0 + ch * 8;
        CP_ASYNC16(sbase + 2 * ML_A_OPB + 0 * ML_B_OPB + doff, Bh + go);
        CP_ASYNC16(sbase + 2 * ML_A_OPB + 1 * ML_B_OPB + doff, Bl + go);
    }
}

__global__ void __launch_bounds__(256, 2)
mlp_gemm(const __half* __restrict__ Ah, const __half* __restrict__ Al,
         const __half* __restrict__ Bh, const __half* __restrict__ Bl,
         const float* __restrict__ bias,
         __half* __restrict__ Oh, __half* __restrict__ Ol,
         float* __restrict__ Of) {
    extern __shared__ __half hsm[];
    const uint32_t smem_u32 = smem_to_u32(hsm);
    const int tid = threadIdx.x;
    const int lane = tid & 31, wid = tid >> 5;
    const int m0 = blockIdx.y * 32, n0 = blockIdx.x * 128;
    const int wm = (wid >> 2) * 16, wn = (wid & 3) * 32;
    const int g = lane >> 2, tg = lane & 3;
    const int lrow = lane & 15, lsel = lane >> 4, lsw = lrow & 7;

    const uint32_t rA0 = (uint32_t)((wm + lrow) * 128);
    const uint32_t rB0 = (uint32_t)((wn + lrow) * 128);
    const uint32_t rB1 = (uint32_t)((wn + 16 + lrow) * 128);

    float acc[4][4];
    uint32_t accc[4][2];
#pragma unroll
    for (int j = 0; j < 4; j++) {
#pragma unroll
        for (int r = 0; r < 4; r++) acc[j][r] = 0.0f;
        accc[j][0] = 0u; accc[j][1] = 0u;
    }

    ml_issue(0, m0, n0, smem_u32, tid, Ah, Al, Bh, Bl);
    CP_COMMIT();

    for (int c = 0; c < NCH; c++) {
        CP_WAIT0();
        __syncthreads();
        if (c + 1 < NCH) {
            ml_issue(c + 1, m0, n0, smem_u32, tid, Ah, Al, Bh, Bl);
            CP_COMMIT();
        }
        const uint32_t sb = smem_u32 + (c & 1) * ML_STAGEB;
        const uint32_t aH = sb, aL = sb + ML_A_OPB;
        const uint32_t bH = sb + 2 * ML_A_OPB, bL = bH + ML_B_OPB;

#pragma unroll
        for (int ks = 0; ks < KC2 / 16; ks++) {
            const uint32_t swz = (uint32_t)((((ks * 2) + lsel) ^ lsw) * 16);
            uint32_t a_hi[4], a_lo[4], b_hi[2][4], b_lo[2][4];

            LDSM4(a_hi[0], a_hi[1], a_hi[2], a_hi[3], aH + rA0 + swz);
            LDSM4(b_hi[0][0], b_hi[0][1], b_hi[0][2], b_hi[0][3], bH + rB0 + swz);
            LDSM4(b_hi[1][0], b_hi[1][1], b_hi[1][2], b_hi[1][3], bH + rB1 + swz);
#pragma unroll
            for (int nf = 0; nf < 4; nf++) {
                int p = nf >> 1, o = nf & 1;
                uint32_t bf[2] = { b_hi[p][o], b_hi[p][o + 2] };
                mma16816(acc[nf], a_hi, bf);
            }
            LDSM4(b_lo[0][0], b_lo[0][1], b_lo[0][2], b_lo[0][3], bL + rB0 + swz);
            LDSM4(b_lo[1][0], b_lo[1][1], b_lo[1][2], b_lo[1][3], bL + rB1 + swz);
#pragma unroll
            for (int nf = 0; nf < 4; nf++) {
                int p = nf >> 1, o = nf & 1;
                uint32_t bf[2] = { b_lo[p][o], b_lo[p][o + 2] };
                mma16816_f16(accc[nf], a_hi, bf);
            }
            LDSM4(a_lo[0], a_lo[1], a_lo[2], a_lo[3], aL + rA0 + swz);
#pragma unroll
            for (int nf = 0; nf < 4; nf++) {
                int p = nf >> 1, o = nf & 1;
                uint32_t bf[2] = { b_hi[p][o], b_hi[p][o + 2] };
                mma16816_f16(accc[nf], a_lo, bf);
            }
        }
        __syncthreads();
    }

    // Epilogue: relu(acc + corr + bias) -> fp32 Of and split (Oh, Ol)
#pragma unroll
    for (int nf = 0; nf < 4; nf++) {
        int col = n0 + wn + nf * 8 + tg * 2;
        float b0 = bias[col], b1 = bias[col + 1];
        __half2 c01 = *(__half2*)&accc[nf][0];
        __half2 c23 = *(__half2*)&accc[nf][1];
        int r0 = m0 + wm + g;
        float v0 = fmaxf(acc[nf][0] + __low2float(c01)  + b0, 0.0f);
        float v1 = fmaxf(acc[nf][1] + __high2float(c01) + b1, 0.0f);
        float v2 = fmaxf(acc[nf][2] + __low2float(c23)  + b0, 0.0f);
        float v3 = fmaxf(acc[nf][3] + __high2float(c23) + b1, 0.0f);
        float2 w0 = {v0, v1}, w1 = {v2, v3};
        *(float2*)(Of + (size_t)r0 * DIM + col) = w0;
        *(float2*)(Of + (size_t)(r0 + 8) * DIM + col) = w1;
        __half h0 = __float2half_rn(v0), h1 = __float2half_rn(v1);
        __half h2 = __float2half_rn(v2), h3 = __float2half_rn(v3);
        *(__half2*)(Oh + (size_t)r0 * DIM + col) = __halves2half2(h0, h1);
        *(__half2*)(Ol + (size_t)r0 * DIM + col) =
            __halves2half2(__float2half_rn(v0 - __half2float(h0)),
                           __float2half_rn(v1 - __half2float(h1)));
        *(__half2*)(Oh + (size_t)(r0 + 8) * DIM + col) = __halves2half2(h2, h3);
        *(__half2*)(Ol + (size_t)(r0 + 8) * DIM + col) =
            __halves2half2(__float2half_rn(v2 - __half2float(h2)),
                           __float2half_rn(v3 - __half2float(h3)));
    }
}

// ---------------------------------------------------------------------------
// 6) Final projection: out[b] = molf[b,:] . Wp + bp
// ---------------------------------------------------------------------------
__global__ void final_kernel(const float* __restrict__ Wp,
                             const float* __restrict__ bp,
                             float* __restrict__ out) {
    int b = blockIdx.x;
    float s = 0.0f;
    for (int d = threadIdx.x; d < DIM; d += 128)
        s = fmaf(g_molf[(size_t)b * DIM + d], Wp[d], s);
    __shared__ float red[4];
#pragma unroll
    for (int o = 16; o; o >>= 1) s += __shfl_down_sync(0xFFFFFFFFu, s, o);
    if ((threadIdx.x & 31) == 0) red[threadIdx.x >> 5] = s;
    __syncthreads();
    if (threadIdx.x == 0)
        out[b] = red[0] + red[1] + red[2] + red[3] + bp[0];
}

// ---------------------------------------------------------------------------
// Launcher
// ---------------------------------------------------------------------------
extern "C" void kernel_launch(void* const* d_in, const int* in_sizes, int n_in,
                              void* d_out, int out_size) {
    const int*   fp    = (const int*)  d_in[0];
    const float* adj   = (const float*)d_in[1];
    const float* embed = (const float*)d_in[2];
    const float* Wf    = (const float*)d_in[3];
    const float* bf    = (const float*)d_in[4];
    const float* Wo    = (const float*)d_in[5];
    const float* bo    = (const float*)d_in[6];
    const float* Wp    = (const float*)d_in[7];
    const float* bp    = (const float*)d_in[8];
    float* out = (float*)d_out;

    float *H, *Molf;
    __half *Vh, *Vl, *Wth, *Wtl, *Woth, *Wotl, *Mh0, *Ml0, *Mh1, *Ml1;
    cudaGetSymbolAddress((void**)&H,    g_H);
    cudaGetSymbolAddress((void**)&Vh,   g_Vh);
    cudaGetSymbolAddress((void**)&Vl,   g_Vl);
    cudaGetSymbolAddress((void**)&Wth,  g_Wth);
    cudaGetSymbolAddress((void**)&Wtl,  g_Wtl);
    cudaGetSymbolAddress((void**)&Woth, g_Woth);
    cudaGetSymbolAddress((void**)&Wotl, g_Wotl);
    cudaGetSymbolAddress((void**)&Mh0,  g_Mh0);
    cudaGetSymbolAddress((void**)&Ml0,  g_Ml0);
    cudaGetSymbolAddress((void**)&Mh1,  g_Mh1);
    cudaGetSymbolAddress((void**)&Ml1,  g_Ml1);
    cudaGetSymbolAddress((void**)&Molf, g_molf);

    cudaFuncSetAttribute(hgemm_fused,
                         cudaFuncAttributeMaxDynamicSharedMemorySize, HG_SMEM);
    cudaFuncSetAttribute(mlp_gemm,
                         cudaFuncAttributeMaxDynamicSharedMemorySize, ML_SMEM);
    cudaFuncSetAttribute(final_pool_kernel,
                         cudaFuncAttributeMaxDynamicSharedMemorySize, POOL_SMEM);

    transpose_split_w<<<dim3(16, 16, LHID), dim3(32, 8)>>>(Wf, Wth, Wtl);   // 0
    transpose_split_w<<<dim3(16, 16, LOUT), dim3(32, 8)>>>(Wo, Woth, Wotl); // 1
    gather_embed<<<NROWS / 2, 256>>>(fp, embed);                            // 2

    for (int l = 0; l < LHID; l++) {
        hgemm_fused<<<dim3(DIM / 128, NROWS / 64), HG_THREADS, HG_SMEM>>>(
            Vh, Vl,
            Wth + (size_t)l * DIM * DIM, Wtl + (size_t)l * DIM * DIM,
            bf + (size_t)l * DIM, adj, H);                                  // 3 (l0), 5 (l1) <- ncu
        if (l + 1 < LHID)
            norm_split_kernel<<<NROWS / 8, 256>>>();
        else
            final_pool_kernel<<<BATCH, 256, POOL_SMEM>>>();
    }

    __half *sh = Mh0, *sl = Ml0, *dh = Mh1, *dl = Ml1;
    for (int i = 0; i < LOUT; i++) {
        mlp_gemm<<<dim3(DIM / 128, BATCH / 32), 256, ML_SMEM>>>(
            sh, sl,
            Woth + (size_t)i * DIM * DIM, Wotl + (size_t)i * DIM * DIM,
            bo + (size_t)i * DIM, dh, dl, Molf);
        __half* t;
        t = sh; sh = dh; dh = t;
        t = sl; sl = dl; dl = t;
    }

    final_kernel<<<BATCH, 128>>>(Wp, bp, out);
}